// round 2
// baseline (speedup 1.0000x reference)
#include <cuda_runtime.h>

#define NN 50000
#define NE 800000

// ---------------- scratch (device globals; no allocation) ----------------
__device__ __align__(16) float g_deg[NN];
__device__ __align__(16) float g_invdeg[NN];
__device__ __align__(16) float g_lin[NN * 64];   // [N][2*FO] : cols [0,FO)=h@Ws, [FO,2FO)=h@Wn
__device__ __align__(16) float g_agg[NN * 32];   // [N][FO]
__device__ __align__(16) float g_h[NN * 32];     // hidden activations (reused across layers)

// ---------------- degree ----------------
__global__ void deg_kernel(const int* __restrict__ dst) {
    int e = blockIdx.x * blockDim.x + threadIdx.x;
    if (e < NE) atomicAdd(&g_deg[dst[e]], 1.0f);
}

__global__ void invdeg_kernel() {
    int i = blockIdx.x * blockDim.x + threadIdx.x;
    if (i < NN) g_invdeg[i] = 1.0f / fmaxf(g_deg[i], 1.0f);
}

// ---------------- dense transform: out[node][c] = h[node] . W[:,c] ----------------
// One thread per output column; W column held in registers; h tile staged in shared.
template <int K, int FO, int NPI>
__global__ void gemm_kernel(const float* __restrict__ h,
                            const float* __restrict__ Ws,
                            const float* __restrict__ Wn,
                            float* __restrict__ outp) {
    constexpr int COLS = 2 * FO;
    __shared__ float sh[NPI * K];
    const int tid = threadIdx.x;
    const int c = tid % COLS;
    const int r = tid / COLS;

    float w[K];
    const float* W = (c < FO) ? Ws : Wn;
    const int cc = (c < FO) ? c : (c - FO);
#pragma unroll
    for (int k = 0; k < K; k++) w[k] = W[k * FO + cc];

    const int ntiles = (NN + NPI - 1) / NPI;
    for (int tile = blockIdx.x; tile < ntiles; tile += gridDim.x) {
        const int base = tile * NPI;
        __syncthreads();
        for (int idx = tid; idx < NPI * K; idx += blockDim.x) {
            const int rr = idx / K;
            const int kk = idx - rr * K;
            const int node = base + rr;
            sh[idx] = (node < NN) ? h[node * K + kk] : 0.0f;
        }
        __syncthreads();
        const int node = base + r;
        if (node < NN) {
            float acc = 0.0f;
#pragma unroll
            for (int k = 0; k < K; k += 4) {
                float4 hv = *reinterpret_cast<const float4*>(&sh[r * K + k]);
                acc += hv.x * w[k] + hv.y * w[k + 1] + hv.z * w[k + 2] + hv.w * w[k + 3];
            }
            outp[node * COLS + c] = acc;
        }
    }
}

// small layer-2 transform: 2 output cols per node
__global__ void gemm2_kernel(const float* __restrict__ h,
                             const float* __restrict__ Ws,
                             const float* __restrict__ Wn,
                             float* __restrict__ outp) {
    __shared__ float ws[16], wn[16];
    if (threadIdx.x < 16) {
        ws[threadIdx.x] = Ws[threadIdx.x];
        wn[threadIdx.x] = Wn[threadIdx.x];
    }
    __syncthreads();
    int i = blockIdx.x * blockDim.x + threadIdx.x;
    if (i >= NN) return;
    float as = 0.0f, an = 0.0f;
#pragma unroll
    for (int k = 0; k < 16; k += 4) {
        float4 hv = *reinterpret_cast<const float4*>(h + i * 16 + k);
        as += hv.x * ws[k] + hv.y * ws[k + 1] + hv.z * ws[k + 2] + hv.w * ws[k + 3];
        an += hv.x * wn[k] + hv.y * wn[k + 1] + hv.z * wn[k + 2] + hv.w * wn[k + 3];
    }
    outp[i * 2] = as;
    outp[i * 2 + 1] = an;
}

// ---------------- edge scatter: agg[dst] += ew * (h@Wn)[src] ----------------
// FO/4 threads per edge, each handles one float4; vector RED to L2.
template <int FO>
__global__ void edge_kernel(const int* __restrict__ src,
                            const int* __restrict__ dst,
                            const float* __restrict__ ew,
                            const float* __restrict__ lin,   // [N][2*FO], hn part at +FO
                            float* __restrict__ agg) {       // [N][FO]
    constexpr int TPE = FO / 4;
    const long long tid = (long long)blockIdx.x * blockDim.x + threadIdx.x;
    const int e = (int)(tid / TPE);
    const int q = (int)(tid % TPE);
    if (e >= NE) return;
    const int s = __ldg(src + e);
    const int d = __ldg(dst + e);
    const float w = __ldg(ew + e);
    float4 v = *reinterpret_cast<const float4*>(lin + (size_t)s * (2 * FO) + FO + 4 * q);
    float* p = agg + (size_t)d * FO + 4 * q;
    asm volatile("red.global.add.v4.f32 [%0], {%1, %2, %3, %4};"
                 :: "l"(p), "f"(v.x * w), "f"(v.y * w), "f"(v.z * w), "f"(v.w * w)
                 : "memory");
}

// layer-2 edge scatter (1 float per edge)
__global__ void edge2_kernel(const int* __restrict__ src,
                             const int* __restrict__ dst,
                             const float* __restrict__ ew,
                             const float* __restrict__ lin,  // [N][2], hn at col 1
                             float* __restrict__ agg) {
    int e = blockIdx.x * blockDim.x + threadIdx.x;
    if (e >= NE) return;
    atomicAdd(agg + __ldg(dst + e), lin[__ldg(src + e) * 2 + 1] * __ldg(ew + e));
}

// ---------------- node epilogue: out = hs + agg/deg + b (opt tanh) ----------------
template <int FO, bool ACT>
__global__ void node_kernel(const float* __restrict__ lin,
                            const float* __restrict__ agg,
                            const float* __restrict__ b,
                            float* __restrict__ outp) {
    int tid = blockIdx.x * blockDim.x + threadIdx.x;
    if (tid >= NN * FO) return;
    const int i = tid / FO;
    const int j = tid - i * FO;
    float v = lin[i * 2 * FO + j] + agg[tid] * g_invdeg[i] + b[j];
    outp[tid] = ACT ? tanhf(v) : v;
}

// ---------------- launch ----------------
extern "C" void kernel_launch(void* const* d_in, const int* in_sizes, int n_in,
                              void* d_out, int out_size) {
    (void)in_sizes; (void)n_in; (void)out_size;
    const float* b_z = (const float*)d_in[0];
    const int*   src = (const int*)d_in[1];
    const int*   dst = (const int*)d_in[2];
    const float* ew  = (const float*)d_in[3];
    const float* Ws0 = (const float*)d_in[4];
    const float* Wn0 = (const float*)d_in[5];
    const float* b0  = (const float*)d_in[6];
    const float* Ws1 = (const float*)d_in[7];
    const float* Wn1 = (const float*)d_in[8];
    const float* b1  = (const float*)d_in[9];
    const float* Ws2 = (const float*)d_in[10];
    const float* Wn2 = (const float*)d_in[11];
    const float* b2  = (const float*)d_in[12];
    float* outp = (float*)d_out;

    float *p_deg, *p_lin, *p_agg, *p_h;
    cudaGetSymbolAddress((void**)&p_deg, g_deg);
    cudaGetSymbolAddress((void**)&p_lin, g_lin);
    cudaGetSymbolAddress((void**)&p_agg, g_agg);
    cudaGetSymbolAddress((void**)&p_h,   g_h);

    cudaStream_t s = 0;

    // degree (shared across all layers)
    cudaMemsetAsync(p_deg, 0, NN * sizeof(float), s);
    deg_kernel<<<(NE + 255) / 256, 256, 0, s>>>(dst);
    invdeg_kernel<<<(NN + 255) / 256, 256, 0, s>>>();

    // ---- layer 0: 64 -> 32, tanh ----
    gemm_kernel<64, 32, 4><<<592, 256, 0, s>>>(b_z, Ws0, Wn0, p_lin);
    cudaMemsetAsync(p_agg, 0, NN * 32 * sizeof(float), s);
    edge_kernel<32><<<((long long)NE * 8 + 255) / 256, 256, 0, s>>>(src, dst, ew, p_lin, p_agg);
    node_kernel<32, true><<<(NN * 32 + 255) / 256, 256, 0, s>>>(p_lin, p_agg, b0, p_h);

    // ---- layer 1: 32 -> 16, tanh ----
    gemm_kernel<32, 16, 8><<<592, 256, 0, s>>>(p_h, Ws1, Wn1, p_lin);
    cudaMemsetAsync(p_agg, 0, NN * 16 * sizeof(float), s);
    edge_kernel<16><<<((long long)NE * 4 + 255) / 256, 256, 0, s>>>(src, dst, ew, p_lin, p_agg);
    node_kernel<16, true><<<(NN * 16 + 255) / 256, 256, 0, s>>>(p_lin, p_agg, b1, p_h);

    // ---- layer 2: 16 -> 1, no activation ----
    gemm2_kernel<<<(NN + 255) / 256, 256, 0, s>>>(p_h, Ws2, Wn2, p_lin);
    cudaMemsetAsync(p_agg, 0, NN * sizeof(float), s);
    edge2_kernel<<<(NE + 255) / 256, 256, 0, s>>>(src, dst, ew, p_lin, p_agg);
    node_kernel<1, false><<<(NN + 255) / 256, 256, 0, s>>>(p_lin, p_agg, b2, outp);
}